// round 16
// baseline (speedup 1.0000x reference)
#include <cuda_runtime.h>
#include <cuda_bf16.h>
#include <math.h>
#include <mma.h>
#include <cstdint>

using namespace nvcuda;

#define NPTS 100000
#define SS 16
#define CC 256
#define GG 16
#define NSROWS (NPTS*SS)

// ---------------- scratch (__device__ globals, per harness rules) ----------------
__device__ float g_Qlin[NPTS*CC];
__device__ float g_Klin[NPTS*CC];
__device__ float g_V[NPTS*CC];
__device__ float g_qg[NPTS*GG];
__device__ float g_kg[NPTS*GG];
__device__ float g_wpre[NPTS*SS*GG];
__device__ __nv_bfloat16 g_HwH[(size_t)NPTS*GG*CC];   // [n][g][c'] bf16 hi
__device__ __nv_bfloat16 g_HwL[(size_t)NPTS*GG*CC];   // [n][g][c'] bf16 lo
__device__ __nv_bfloat16 g_featH[NPTS*CC];
__device__ __nv_bfloat16 g_featL[NPTS*CC];
__device__ __nv_bfloat16 g_WH[3*CC*CC];
__device__ __nv_bfloat16 g_WL[3*CC*CC];
__device__ double g_ds[1100];
// layout: 0 qsum[256], 256 qsq[256], 512 ksum[256], 768 ksq[256],
//         1024 posmom[9], 1040 wsum[16], 1056 wsq[16]
__device__ float g_aq[CC], g_bq[CC], g_ak[CC], g_bk[CC], g_ap[CC], g_bpf[CC];
__device__ __nv_bfloat16 g_Wp2gH[CC*GG];  // [c'][g] hi
__device__ __nv_bfloat16 g_Wp2gL[CC*GG];  // [c'][g] lo
__device__ float g_glb[GG];
__device__ float g_aw[GG], g_bw[GG];

// ---------------- K0: zero accumulators ----------------
__global__ void k_zero() {
    int t = blockIdx.x * 256 + threadIdx.x;
    if (t < 1100) g_ds[t] = 0.0;
}

// ---------------- bf16 hi/lo split helpers ----------------
__device__ __forceinline__ void split4(float4 v, __nv_bfloat162* h, __nv_bfloat162* l) {
    float xs[4] = {v.x, v.y, v.z, v.w};
    __nv_bfloat16 hh[4], ll[4];
#pragma unroll
    for (int i = 0; i < 4; i++) {
        hh[i] = __float2bfloat16_rn(xs[i]);
        ll[i] = __float2bfloat16_rn(xs[i] - __bfloat162float(hh[i]));
    }
    h[0] = __nv_bfloat162(hh[0], hh[1]);
    h[1] = __nv_bfloat162(hh[2], hh[3]);
    l[0] = __nv_bfloat162(ll[0], ll[1]);
    l[1] = __nv_bfloat162(ll[2], ll[3]);
}

// ---------------- K-cvt: one-time fp32 -> bf16 hi/lo ----------------
__global__ void k_cvt_feat(const float* __restrict__ feat) {
    size_t i = ((size_t)blockIdx.x * 256 + threadIdx.x) * 4;   // grid 25000, exact
    float4 v = *(const float4*)(feat + i);
    split4(v, (__nv_bfloat162*)(g_featH + i), (__nv_bfloat162*)(g_featL + i));
}

__global__ void k_cvt_W(const float* __restrict__ Wq, const float* __restrict__ Wk,
                        const float* __restrict__ Wv) {
    size_t i = ((size_t)blockIdx.x * 256 + threadIdx.x) * 4;   // grid 192, exact (196608)
    const float* W = (i < 65536) ? Wq : ((i < 131072) ? Wk : Wv);
    size_t off = i & 65535;
    float4 v = *(const float4*)(W + off);
    split4(v, (__nv_bfloat162*)(g_WH + i), (__nv_bfloat162*)(g_WL + i));
}

// ---------------- cp.async helpers ----------------
__device__ __forceinline__ void cp16(void* dst, const void* src) {
    unsigned int d = (unsigned int)__cvta_generic_to_shared(dst);
    asm volatile("cp.async.cg.shared.global [%0], [%1], 16;\n" :: "r"(d), "l"(src));
}
__device__ __forceinline__ void cp_commit() {
    asm volatile("cp.async.commit_group;\n");
}
template <int N>
__device__ __forceinline__ void cp_wait() {
    asm volatile("cp.async.wait_group %0;\n" :: "n"(N));
}

// ---------------- K1: QKV GEMM, bf16x3 split wmma (unchanged, proven) ----------------
#define STG_BYTES 37888
#define GEMM_SMEM (2*STG_BYTES)

__global__ void __launch_bounds__(256, 2) k_gemm_tc(
    const float* __restrict__ bq, const float* __restrict__ bk,
    const float* __restrict__ bv)
{
    extern __shared__ __align__(16) char sm[];

    int mat = blockIdx.y >> 1;
    int n0  = (blockIdx.y & 1) << 7;
    int m0  = blockIdx.x << 7;
    const __nv_bfloat16* WH = g_WH + mat * 65536;
    const __nv_bfloat16* WL = g_WL + mat * 65536;
    const float* bias = (mat == 0) ? bq : ((mat == 1) ? bk : bv);
    float* out        = (mat == 0) ? g_Qlin : ((mat == 1) ? g_Klin : g_V);

    int t = threadIdx.x;
    int warp = t >> 5, lane = t & 31;
    int wm = warp & 3, wn = warp >> 2;

    int ar0 = t >> 2,        ac = (t & 3) * 8;
    int br0 = t >> 4,        bc = (t & 15) * 8;
    int gm0 = m0 + ar0;       if (gm0 >= NPTS) gm0 = NPTS - 1;
    int gm1 = m0 + ar0 + 64;  if (gm1 >= NPTS) gm1 = NPTS - 1;

    wmma::fragment<wmma::accumulator, 16, 16, 16, float> acc[2][4];
#pragma unroll
    for (int i = 0; i < 2; i++)
#pragma unroll
        for (int j = 0; j < 4; j++) wmma::fill_fragment(acc[i][j], 0.f);

    auto issue = [&](int c, int s) {
        char* base = sm + s * STG_BYTES;
        __nv_bfloat16 (*Ah)[40]  = (__nv_bfloat16(*)[40])(base);
        __nv_bfloat16 (*Al)[40]  = (__nv_bfloat16(*)[40])(base + 10240);
        __nv_bfloat16 (*Bh)[136] = (__nv_bfloat16(*)[136])(base + 20480);
        __nv_bfloat16 (*Bl)[136] = (__nv_bfloat16(*)[136])(base + 29184);
        int k0 = c * 32;
        cp16(&Ah[ar0][ac],      g_featH + (size_t)gm0 * CC + k0 + ac);
        cp16(&Ah[ar0 + 64][ac], g_featH + (size_t)gm1 * CC + k0 + ac);
        cp16(&Al[ar0][ac],      g_featL + (size_t)gm0 * CC + k0 + ac);
        cp16(&Al[ar0 + 64][ac], g_featL + (size_t)gm1 * CC + k0 + ac);
        cp16(&Bh[br0][bc],      WH + (size_t)(k0 + br0) * CC + n0 + bc);
        cp16(&Bh[br0 + 16][bc], WH + (size_t)(k0 + br0 + 16) * CC + n0 + bc);
        cp16(&Bl[br0][bc],      WL + (size_t)(k0 + br0) * CC + n0 + bc);
        cp16(&Bl[br0 + 16][bc], WL + (size_t)(k0 + br0 + 16) * CC + n0 + bc);
        cp_commit();
    };

    issue(0, 0);
    issue(1, 1);

    for (int c = 0; c < 8; c++) {
        if (c + 1 < 8) cp_wait<1>(); else cp_wait<0>();
        __syncthreads();
        char* base = sm + (c & 1) * STG_BYTES;
        __nv_bfloat16 (*Ah)[40]  = (__nv_bfloat16(*)[40])(base);
        __nv_bfloat16 (*Al)[40]  = (__nv_bfloat16(*)[40])(base + 10240);
        __nv_bfloat16 (*Bh)[136] = (__nv_bfloat16(*)[136])(base + 20480);
        __nv_bfloat16 (*Bl)[136] = (__nv_bfloat16(*)[136])(base + 29184);
#pragma unroll
        for (int kk = 0; kk < 32; kk += 16) {
            wmma::fragment<wmma::matrix_a, 16, 16, 16, __nv_bfloat16, wmma::row_major> ah[2], al[2];
#pragma unroll
            for (int i = 0; i < 2; i++) {
                wmma::load_matrix_sync(ah[i], &Ah[wm * 32 + i * 16][kk], 40);
                wmma::load_matrix_sync(al[i], &Al[wm * 32 + i * 16][kk], 40);
            }
#pragma unroll
            for (int j = 0; j < 4; j++) {
                wmma::fragment<wmma::matrix_b, 16, 16, 16, __nv_bfloat16, wmma::row_major> bh, bl;
                wmma::load_matrix_sync(bh, &Bh[kk][wn * 64 + j * 16], 136);
                wmma::load_matrix_sync(bl, &Bl[kk][wn * 64 + j * 16], 136);
#pragma unroll
                for (int i = 0; i < 2; i++) {
                    wmma::mma_sync(acc[i][j], ah[i], bh, acc[i][j]);
                    wmma::mma_sync(acc[i][j], ah[i], bl, acc[i][j]);
                    wmma::mma_sync(acc[i][j], al[i], bh, acc[i][j]);
                }
            }
        }
        __syncthreads();
        if (c + 2 < 8) issue(c + 2, c & 1);
    }

    float (*ob)[68] = (float(*)[68])(sm + warp * 8704);
#pragma unroll
    for (int i = 0; i < 2; i++)
#pragma unroll
        for (int j = 0; j < 4; j++)
            wmma::store_matrix_sync(&ob[i * 16][j * 16], acc[i][j], 68, wmma::mem_row_major);
    __syncwarp();

    int col0 = n0 + wn * 64 + lane;
    int col1 = col0 + 32;
    float bb0 = bias[col0], bb1 = bias[col1];
    float s1a = 0.f, s2a = 0.f, s1b = 0.f, s2b = 0.f;
#pragma unroll
    for (int r = 0; r < 32; r++) {
        int gm = m0 + wm * 32 + r;
        if (gm < NPTS) {
            float v0 = ob[r][lane] + bb0;
            float v1 = ob[r][lane + 32] + bb1;
            out[(size_t)gm * CC + col0] = v0;
            out[(size_t)gm * CC + col1] = v1;
            s1a += v0; s2a = fmaf(v0, v0, s2a);
            s1b += v1; s2b = fmaf(v1, v1, s2b);
        }
    }
    if (mat < 2) {
        int base = (mat == 0) ? 0 : 512;
        atomicAdd(&g_ds[base + col0],       (double)s1a);
        atomicAdd(&g_ds[base + 256 + col0], (double)s2a);
        atomicAdd(&g_ds[base + col1],       (double)s1b);
        atomicAdd(&g_ds[base + 256 + col1], (double)s2b);
    }
}

// ---------------- K3: pos second moments ----------------
__global__ void k_posmom(const float* __restrict__ coord, const int* __restrict__ ridx) {
    int i = blockIdx.x * 256 + threadIdx.x;
    int n = i >> 4;
    int r = ridx[i];
    float px = 0, py = 0, pz = 0;
    if (r >= 0) {
        px = coord[r * 3 + 0] - coord[n * 3 + 0];
        py = coord[r * 3 + 1] - coord[n * 3 + 1];
        pz = coord[r * 3 + 2] - coord[n * 3 + 2];
    }
    float v[9] = {px, py, pz, px * px, py * py, pz * pz, px * py, px * pz, py * pz};
    __shared__ float red[8][9];
    int lane = threadIdx.x & 31, w = threadIdx.x >> 5;
#pragma unroll
    for (int j = 0; j < 9; j++)
#pragma unroll
        for (int off = 16; off; off >>= 1)
            v[j] += __shfl_down_sync(0xffffffffu, v[j], off);
    if (lane == 0)
#pragma unroll
        for (int j = 0; j < 9; j++) red[w][j] = v[j];
    __syncthreads();
    if (threadIdx.x < 9) {
        float s = 0;
        for (int w2 = 0; w2 < 8; w2++) s += red[w2][threadIdx.x];
        atomicAdd(&g_ds[1024 + threadIdx.x], (double)s);
    }
}

// ---------------- K4: fold BN params; build Wp2g (hi/lo), glb ----------------
__global__ void k_final1(
    const float* __restrict__ gq, const float* __restrict__ betaq,
    const float* __restrict__ gk, const float* __restrict__ betak,
    const float* __restrict__ Wp1, const float* __restrict__ bp1,
    const float* __restrict__ gp, const float* __restrict__ betap,
    const float* __restrict__ Wp2, const float* __restrict__ bp2,
    const float* __restrict__ w_gl)
{
    int c = threadIdx.x;
    double invN = 1.0 / (double)NPTS;
    {
        double mu = g_ds[c] * invN;
        double var = g_ds[256 + c] * invN - mu * mu;
        float a = (float)((double)gq[c] / sqrt(var + 1e-5));
        g_aq[c] = a; g_bq[c] = betaq[c] - (float)mu * a;
    }
    {
        double mu = g_ds[512 + c] * invN;
        double var = g_ds[768 + c] * invN - mu * mu;
        float a = (float)((double)gk[c] / sqrt(var + 1e-5));
        g_ak[c] = a; g_bk[c] = betak[c] - (float)mu * a;
    }
    {
        double sx = g_ds[1024], sy = g_ds[1025], sz = g_ds[1026];
        double xx = g_ds[1027], yy = g_ds[1028], zz = g_ds[1029];
        double xy = g_ds[1030], xz = g_ds[1031], yz = g_ds[1032];
        double w0 = Wp1[c], w1 = Wp1[256 + c], w2 = Wp1[512 + c], b = bp1[c];
        double invNS = 1.0 / (double)NSROWS;
        double sw = sx * w0 + sy * w1 + sz * w2;
        double mean = sw * invNS + b;
        double ex2 = (w0 * w0 * xx + w1 * w1 * yy + w2 * w2 * zz
                      + 2.0 * (w0 * w1 * xy + w0 * w2 * xz + w1 * w2 * yz)
                      + 2.0 * b * sw) * invNS + b * b;
        double var = ex2 - mean * mean;
        float a = (float)((double)gp[c] / sqrt(var + 1e-5));
        g_ap[c]  = a;
        g_bpf[c] = (float)((double)a * b + (double)betap[c] - mean * a);
    }
#pragma unroll
    for (int g = 0; g < GG; g++) {
        float s = 0;
#pragma unroll
        for (int i2 = 0; i2 < 16; i2++)
            s = fmaf(Wp2[(size_t)c * CC + g * 16 + i2], w_gl[g * 16 + i2], s);
        __nv_bfloat16 hh = __float2bfloat16_rn(s);
        g_Wp2gH[c * GG + g] = hh;
        g_Wp2gL[c * GG + g] = __float2bfloat16_rn(s - __bfloat162float(hh));
    }
    if (c < GG) {
        float s = 0;
#pragma unroll
        for (int i2 = 0; i2 < 16; i2++) s = fmaf(bp2[c * 16 + i2], w_gl[c * 16 + i2], s);
        g_glb[c] = s;
    }
}

// ---------------- K5: group-folded q,k vectors ----------------
__global__ void __launch_bounds__(256) k_qkgroup(const float* __restrict__ w_gl) {
    int lane = threadIdx.x & 31, warp = threadIdx.x >> 5;
    int n = blockIdx.x * 8 + warp;
#pragma unroll
    for (int j = 0; j < 8; j++) {
        int c = lane + 32 * j;
        float wg = w_gl[c];
        float vq = fmaxf(fmaf(g_aq[c], g_Qlin[(size_t)n * CC + c], g_bq[c]), 0.f) * wg;
        float vk = fmaxf(fmaf(g_ak[c], g_Klin[(size_t)n * CC + c], g_bk[c]), 0.f) * wg;
#pragma unroll
        for (int off = 8; off; off >>= 1) {
            vq += __shfl_down_sync(0xffffffffu, vq, off, 16);
            vk += __shfl_down_sync(0xffffffffu, vk, off, 16);
        }
        if (lane == 0)  { g_qg[n * GG + 2 * j]     = vq; g_kg[n * GG + 2 * j]     = vk; }
        if (lane == 16) { g_qg[n * GG + 2 * j + 1] = vq; g_kg[n * GG + 2 * j + 1] = vk; }
    }
}

// ---------------- K6: w_pre logits on tensor cores, h in hi/lo bf16 ----------------
__global__ void __launch_bounds__(256, 2) k_wpre_tc(
    const float* __restrict__ coord, const int* __restrict__ ridx,
    const float* __restrict__ Wp1)
{
    __shared__ __align__(32) __nv_bfloat16 hAh[128][40];
    __shared__ __align__(32) __nv_bfloat16 hAl[128][40];
    __shared__ __align__(32) __nv_bfloat16 BH[256][16];
    __shared__ __align__(32) __nv_bfloat16 BL[256][16];
    __shared__ __align__(16) float4 P4[256];
    __shared__ float Bpf[256];
    __shared__ float px[128], py[128], pz[128];
    __shared__ int rw[128];
    __shared__ float glb_s[16];

    int t = threadIdx.x;
    int warp = t >> 5;
    P4[t] = make_float4(Wp1[t], Wp1[256 + t], Wp1[512 + t], g_ap[t]);
    Bpf[t] = g_bpf[t];
    for (int l = t; l < 4096; l += 256) {
        ((__nv_bfloat16*)BH)[l] = g_Wp2gH[l];
        ((__nv_bfloat16*)BL)[l] = g_Wp2gL[l];
    }
    if (t < 16) glb_s[t] = g_glb[t];
    int base = blockIdx.x * 128;
    if (t < 128) {
        int row = base + t;
        int r = ridx[row];
        rw[t] = r;
        float x = 0, y = 0, z = 0;
        if (r >= 0) {
            int n = row >> 4;
            x = coord[r * 3 + 0] - coord[n * 3 + 0];
            y = coord[r * 3 + 1] - coord[n * 3 + 1];
            z = coord[r * 3 + 2] - coord[n * 3 + 2];
        }
        px[t] = x; py[t] = y; pz[t] = z;
    }
    __syncthreads();

    wmma::fragment<wmma::accumulator, 16, 16, 16, float> acc;
    wmma::fill_fragment(acc, 0.f);
    int rloc = t >> 1, cb = (t & 1) * 16;
    float x = px[rloc], y = py[rloc], z = pz[rloc];

    for (int c = 0; c < 8; c++) {
        int k0 = c * 32;
#pragma unroll
        for (int i = 0; i < 16; i += 2) {
            int c0 = k0 + cb + i;
            float4 p0 = P4[c0], p1 = P4[c0 + 1];
            float h0 = fmaxf(fmaf(p0.w, fmaf(z, p0.z, fmaf(y, p0.y, x * p0.x)), Bpf[c0]), 0.f);
            float h1 = fmaxf(fmaf(p1.w, fmaf(z, p1.z, fmaf(y, p1.y, x * p1.x)), Bpf[c0 + 1]), 0.f);
            __nv_bfloat16 h0h = __float2bfloat16_rn(h0);
            __nv_bfloat16 h1h = __float2bfloat16_rn(h1);
            *(__nv_bfloat162*)&hAh[rloc][cb + i] = __nv_bfloat162(h0h, h1h);
            *(__nv_bfloat162*)&hAl[rloc][cb + i] = __nv_bfloat162(
                __float2bfloat16_rn(h0 - __bfloat162float(h0h)),
                __float2bfloat16_rn(h1 - __bfloat162float(h1h)));
        }
        __syncthreads();
#pragma unroll
        for (int kk = 0; kk < 32; kk += 16) {
            wmma::fragment<wmma::matrix_a, 16, 16, 16, __nv_bfloat16, wmma::row_major> ah, al;
            wmma::load_matrix_sync(ah, &hAh[warp * 16][kk], 40);
            wmma::load_matrix_sync(al, &hAl[warp * 16][kk], 40);
            wmma::fragment<wmma::matrix_b, 16, 16, 16, __nv_bfloat16, wmma::row_major> bh, bl;
            wmma::load_matrix_sync(bh, &BH[k0 + kk][0], 16);
            wmma::load_matrix_sync(bl, &BL[k0 + kk][0], 16);
            wmma::mma_sync(acc, ah, bh, acc);
            wmma::mma_sync(acc, ah, bl, acc);
            wmma::mma_sync(acc, al, bh, acc);
        }
        __syncthreads();
    }
    // epilogue staging aliased onto hAh/hAl region (no longer needed)
    float* epbase = (float*)&hAh[0][0];    // 8 warps x 16 x 24 floats = 12288 B
    wmma::store_matrix_sync(epbase + warp * 384, acc, 24, wmma::mem_row_major);
    __syncthreads();
    {
        int rl2 = t >> 1, gb = (t & 1) * 8;
        int row = base + rl2;
        int n = row >> 4;
        int r = rw[rl2];
        const float* epp = epbase + (rl2 >> 4) * 384 + (rl2 & 15) * 24;
#pragma unroll
        for (int j = 0; j < 8; j++) {
            int g = gb + j;
            float kgv = (r >= 0) ? g_kg[(size_t)r * GG + g] : 0.f;
            g_wpre[(size_t)row * GG + g] = epp[g] + kgv - g_qg[(size_t)n * GG + g] + glb_s[g];
        }
    }
}

// ---------------- K7: group stats of w_pre ----------------
__global__ void k_wstats() {
    __shared__ float ssum[16], ssq[16];
    int t = threadIdx.x;
    if (t < 16) { ssum[t] = 0.f; ssq[t] = 0.f; }
    __syncthreads();
    int g = t & 15;
    float s1 = 0, s2 = 0;
    for (int row = blockIdx.x * 16 + (t >> 4); row < NSROWS; row += gridDim.x * 16) {
        float x = g_wpre[(size_t)row * GG + g];
        s1 += x; s2 = fmaf(x, x, s2);
    }
    atomicAdd(&ssum[g], s1);
    atomicAdd(&ssq[g], s2);
    __syncthreads();
    if (t < 16) {
        atomicAdd(&g_ds[1040 + t], (double)ssum[t]);
        atomicAdd(&g_ds[1056 + t], (double)ssq[t]);
    }
}

// ---------------- K8: fold group BN ----------------
__global__ void k_final2(const float* __restrict__ g_gl, const float* __restrict__ beta_gl) {
    int g = threadIdx.x;
    if (g < 16) {
        double invNS = 1.0 / (double)NSROWS;
        double mu  = g_ds[1040 + g] * invNS;
        double var = g_ds[1056 + g] * invNS - mu * mu;
        float a = (float)((double)g_gl[g] / sqrt(var + 1e-5));
        g_aw[g] = a; g_bw[g] = beta_gl[g] - (float)mu * a;
    }
}

// ---------------- K9: fused per-point: logits -> softmax -> gathered V + Hw hi/lo ----------------
__global__ void __launch_bounds__(256) k_pointG(
    const float* __restrict__ coord, const int* __restrict__ ridx,
    const float* __restrict__ Wp1,  const float* __restrict__ bp2,
    const float* __restrict__ Wwe,  const float* __restrict__ bwe,
    float* __restrict__ out)
{
    __shared__ float rl[16][17];
    __shared__ float lg[16][17];
    __shared__ float wsm[16][17];
    __shared__ float wsum[16];
    __shared__ float Wwe_s[16][16];
    __shared__ float bwe_s[16];
    __shared__ float psx[16], psy[16], psz[16];
    __shared__ int   rs[16];

    int n = blockIdx.x, t = threadIdx.x;
    Wwe_s[t >> 4][t & 15] = Wwe[t];
    if (t < 16) {
        bwe_s[t] = bwe[t];
        int r = ridx[n * SS + t];
        rs[t] = r;
        float x = 0, y = 0, z = 0;
        if (r >= 0) {
            x = coord[r * 3 + 0] - coord[n * 3 + 0];
            y = coord[r * 3 + 1] - coord[n * 3 + 1];
            z = coord[r * 3 + 2] - coord[n * 3 + 2];
        }
        psx[t] = x; psy[t] = y; psz[t] = z;
    }
    int s = t >> 4, g = t & 15;
    {
        float x = g_wpre[(size_t)n * 256 + t];
        rl[s][g] = fmaxf(fmaf(g_aw[g], x, g_bw[g]), 0.f);
    }
    __syncthreads();
    {
        float acc = bwe_s[g];
#pragma unroll
        for (int gp2 = 0; gp2 < 16; gp2++)
            acc = fmaf(rl[s][gp2], Wwe_s[gp2][g], acc);
        lg[s][g] = acc;
    }
    __syncthreads();
    if (t < 16) {
        float m = -1e30f;
#pragma unroll
        for (int ss2 = 0; ss2 < 16; ss2++) m = fmaxf(m, lg[ss2][t]);
        float sum = 0;
        float e[16];
#pragma unroll
        for (int ss2 = 0; ss2 < 16; ss2++) { e[ss2] = expf(lg[ss2][t] - m); sum += e[ss2]; }
        float inv = 1.f / sum;
        float ws = 0;
#pragma unroll
        for (int ss2 = 0; ss2 < 16; ss2++) {
            float w = (rs[ss2] >= 0) ? e[ss2] * inv : 0.f;
            wsm[ss2][t] = w; ws += w;
        }
        wsum[t] = ws;
    }
    __syncthreads();

    int c = t, gc = c >> 4;
    float hw[16];
#pragma unroll
    for (int gg = 0; gg < 16; gg++) hw[gg] = 0.f;
    float out1 = wsum[gc] * bp2[c];
    float w1c = Wp1[c], w2c = Wp1[256 + c], w3c = Wp1[512 + c];
    float apc = g_ap[c], bpc = g_bpf[c];
#pragma unroll
    for (int ss2 = 0; ss2 < 16; ss2++) {
        int r = rs[ss2];
        if (r >= 0) {
            out1 = fmaf(wsm[ss2][gc], g_V[(size_t)r * CC + c], out1);
            float pd = fmaf(psz[ss2], w3c, fmaf(psy[ss2], w2c, psx[ss2] * w1c));
            float h = fmaxf(fmaf(apc, pd, bpc), 0.f);
#pragma unroll
            for (int gg = 0; gg < 16; gg++)
                hw[gg] = fmaf(wsm[ss2][gg], h, hw[gg]);
        }
    }
    out[(size_t)n * CC + c] = out1;
#pragma unroll
    for (int gg = 0; gg < 16; gg++) {
        float v = hw[gg];
        __nv_bfloat16 hh = __float2bfloat16_rn(v);
        size_t idx = (size_t)n * 4096 + gg * 256 + c;
        g_HwH[idx] = hh;
        g_HwL[idx] = __float2bfloat16_rn(v - __bfloat162float(hh));
    }
}

// ---------------- K10: projection GEMM on tensor cores, A hi/lo ----------------
// dynamic smem layout:
//   AsmH[2][128][40] @0      (20480)
//   AsmL[2][128][40] @20480  (20480)
//   BH[256][16]      @40960  (8192)
//   BL[256][16]      @49152  (8192)
#define PROJ_SMEM 57344

__global__ void __launch_bounds__(256, 2) k_projH_tc(
    const float* __restrict__ Wp2, float* __restrict__ out)
{
    extern __shared__ __align__(32) char smp[];
    __nv_bfloat16 (*AsmH)[128][40] = (__nv_bfloat16(*)[128][40])(smp);
    __nv_bfloat16 (*AsmL)[128][40] = (__nv_bfloat16(*)[128][40])(smp + 20480);
    __nv_bfloat16 (*BH)[16] = (__nv_bfloat16(*)[16])(smp + 40960);
    __nv_bfloat16 (*BL)[16] = (__nv_bfloat16(*)[16])(smp + 49152);

    int g = blockIdx.y;
    int n0 = blockIdx.x * 128;
    int t = threadIdx.x;
    int warp = t >> 5;

    for (int l = t; l < 4096; l += 256) {
        float w = Wp2[(size_t)(l >> 4) * CC + g * 16 + (l & 15)];
        __nv_bfloat16 h = __float2bfloat16_rn(w);
        ((__nv_bfloat16*)BH)[l] = h;
        ((__nv_bfloat16*)BL)[l] = __float2bfloat16_rn(w - __bfloat162float(h));
    }

    auto issueA = [&](int c, int s) {
#pragma unroll
        for (int q = 0; q < 2; q++) {
            int idx = t + q * 256;
            int row = idx >> 2, seg = idx & 3;
            int nn = n0 + row; if (nn >= NPTS) nn = NPTS - 1;
            size_t off = (size_t)nn * 4096 + g * 256 + c * 32 + seg * 8;
            cp16(&AsmH[s][row][seg * 8], g_HwH + off);
            cp16(&AsmL[s][row][seg * 8], g_HwL + off);
        }
        cp_commit();
    };
    issueA(0, 0); issueA(1, 1);

    wmma::fragment<wmma::accumulator, 16, 16, 16, float> acc;
    wmma::fill_fragment(acc, 0.f);

    for (int c = 0; c < 8; c++) {
        if (c + 1 < 8) cp_wait<1>(); else cp_wait<0>();
        __syncthreads();
#pragma unroll
        for (int kk = 0; kk < 32; kk += 16) {
            wmma::fragment<wmma::matrix_a, 16, 16, 16, __nv_bfloat16, wmma::row_major> ah, al;
            wmma::load_matrix_sync(ah, &AsmH[c & 1][warp * 16][kk], 40);
            wmma::load_matrix_sync(al, &AsmL[c & 1][warp * 16][kk], 40);
            wmma::fragment<wmma::matrix_b, 16, 16, 16, __nv_bfloat16, wmma::row_major> bh, bl;
            wmma::load_matrix_sync(bh, &BH[c * 32 + kk][0], 16);
            wmma::load_matrix_sync(bl, &BL[c * 32 + kk][0], 16);
            wmma::mma_sync(acc, ah, bh, acc);
            wmma::mma_sync(acc, ah, bl, acc);
            wmma::mma_sync(acc, al, bh, acc);
        }
        __syncthreads();
        if (c + 2 < 8) issueA(c + 2, c & 1);
    }

    float* ep = (float*)smp;   // reuse A smem for epilogue staging (12288 B)
    wmma::store_matrix_sync(ep + warp * 384, acc, 24, wmma::mem_row_major);
    __syncthreads();
    {
        int rl = t >> 1, jb = (t & 1) * 8;
        int nn = n0 + rl;
        if (nn < NPTS) {
            const float* epp = ep + (rl >> 4) * 384 + (rl & 15) * 24 + jb;
            float4* p0 = (float4*)(out + (size_t)nn * CC + g * 16 + jb);
            float4 c0 = p0[0], c1 = p0[1];
            c0.x += epp[0]; c0.y += epp[1]; c0.z += epp[2]; c0.w += epp[3];
            c1.x += epp[4]; c1.y += epp[5]; c1.z += epp[6]; c1.w += epp[7];
            p0[0] = c0; p0[1] = c1;
        }
    }
}

// ---------------- launch ----------------
extern "C" void kernel_launch(void* const* d_in, const int* in_sizes, int n_in,
                              void* d_out, int out_size) {
    const float* feat   = (const float*)d_in[0];
    const float* coord  = (const float*)d_in[1];
    const int*   ridx   = (const int*)  d_in[2];
    const float* Wq     = (const float*)d_in[3];
    const float* bq     = (const float*)d_in[4];
    const float* gq     = (const float*)d_in[5];
    const float* betaq  = (const float*)d_in[6];
    const float* Wk     = (const float*)d_in[7];
    const float* bk     = (const float*)d_in[8];
    const float* gk     = (const float*)d_in[9];
    const float* betak  = (const float*)d_in[10];
    const float* Wv     = (const float*)d_in[11];
    const float* bv     = (const float*)d_in[12];
    const float* Wp1    = (const float*)d_in[13];
    const float* bp1    = (const float*)d_in[14];
    const float* gp     = (const float*)d_in[15];
    const float* betap  = (const float*)d_in[16];
    const float* Wp2    = (const float*)d_in[17];
    const float* bp2    = (const float*)d_in[18];
    const float* w_gl   = (const float*)d_in[19];
    const float* g_gl   = (const float*)d_in[20];
    const float* betagl = (const float*)d_in[21];
    const float* Wwe    = (const float*)d_in[22];
    const float* bwe    = (const float*)d_in[23];
    float* out = (float*)d_out;

    cudaFuncSetAttribute(k_gemm_tc, cudaFuncAttributeMaxDynamicSharedMemorySize, GEMM_SMEM);
    cudaFuncSetAttribute(k_projH_tc, cudaFuncAttributeMaxDynamicSharedMemorySize, PROJ_SMEM);

    k_zero<<<5, 256>>>();
    k_cvt_feat<<<25000, 256>>>(feat);
    k_cvt_W<<<192, 256>>>(Wq, Wk, Wv);
    dim3 gtc((NPTS + 127) / 128, 6);
    k_gemm_tc<<<gtc, 256, GEMM_SMEM>>>(bq, bk, bv);
    k_posmom<<<NSROWS / 256, 256>>>(coord, ridx);
    k_final1<<<1, 256>>>(gq, betaq, gk, betak, Wp1, bp1, gp, betap, Wp2, bp2, w_gl);
    k_qkgroup<<<NPTS / 8, 256>>>(w_gl);
    k_wpre_tc<<<NSROWS / 128, 256>>>(coord, ridx, Wp1);
    k_wstats<<<512, 256>>>();
    k_final2<<<1, 32>>>(g_gl, betagl);
    k_pointG<<<NPTS, 256>>>(coord, ridx, Wp1, bp2, Wwe, bwe, out);
    dim3 gg2((NPTS + 127) / 128, 16);
    k_projH_tc<<<gg2, 256, PROJ_SMEM>>>(Wp2, out);
}

// round 17
// speedup vs baseline: 1.1593x; 1.1593x over previous
#include <cuda_runtime.h>
#include <cuda_bf16.h>
#include <cuda_fp16.h>
#include <math.h>
#include <mma.h>
#include <cstdint>

using namespace nvcuda;

#define NPTS 100000
#define SS 16
#define CC 256
#define GG 16
#define NSROWS (NPTS*SS)

// ---------------- scratch (__device__ globals, per harness rules) ----------------
__device__ float g_Qlin[NPTS*CC];
__device__ float g_Klin[NPTS*CC];
__device__ float g_V[NPTS*CC];
__device__ float g_qg[NPTS*GG];
__device__ float g_kg[NPTS*GG];
__device__ float g_wpre[NPTS*SS*GG];
__device__ __half g_Hw16[(size_t)NPTS*GG*CC];   // [n][g][c'] fp16, 0.82 GB
__device__ __nv_bfloat16 g_featH[NPTS*CC];
__device__ __nv_bfloat16 g_featL[NPTS*CC];
__device__ __nv_bfloat16 g_WH[3*CC*CC];
__device__ __nv_bfloat16 g_WL[3*CC*CC];
__device__ double g_ds[1100];
// layout: 0 qsum[256], 256 qsq[256], 512 ksum[256], 768 ksq[256],
//         1024 posmom[9], 1040 wsum[16], 1056 wsq[16]
__device__ float g_aq[CC], g_bq[CC], g_ak[CC], g_bk[CC], g_ap[CC], g_bpf[CC];
__device__ __half g_Wp2gH[CC*GG];  // [c'][g] hi (fp16)
__device__ __half g_Wp2gL[CC*GG];  // [c'][g] lo (fp16)
__device__ float g_glb[GG];
__device__ float g_aw[GG], g_bw[GG];

// ---------------- K0: zero accumulators ----------------
__global__ void k_zero() {
    int t = blockIdx.x * 256 + threadIdx.x;
    if (t < 1100) g_ds[t] = 0.0;
}

// ---------------- bf16 hi/lo split helpers ----------------
__device__ __forceinline__ void split4(float4 v, __nv_bfloat162* h, __nv_bfloat162* l) {
    float xs[4] = {v.x, v.y, v.z, v.w};
    __nv_bfloat16 hh[4], ll[4];
#pragma unroll
    for (int i = 0; i < 4; i++) {
        hh[i] = __float2bfloat16_rn(xs[i]);
        ll[i] = __float2bfloat16_rn(xs[i] - __bfloat162float(hh[i]));
    }
    h[0] = __nv_bfloat162(hh[0], hh[1]);
    h[1] = __nv_bfloat162(hh[2], hh[3]);
    l[0] = __nv_bfloat162(ll[0], ll[1]);
    l[1] = __nv_bfloat162(ll[2], ll[3]);
}

// ---------------- K-cvt: one-time fp32 -> bf16 hi/lo ----------------
__global__ void k_cvt_feat(const float* __restrict__ feat) {
    size_t i = ((size_t)blockIdx.x * 256 + threadIdx.x) * 4;   // grid 25000, exact
    float4 v = *(const float4*)(feat + i);
    split4(v, (__nv_bfloat162*)(g_featH + i), (__nv_bfloat162*)(g_featL + i));
}

__global__ void k_cvt_W(const float* __restrict__ Wq, const float* __restrict__ Wk,
                        const float* __restrict__ Wv) {
    size_t i = ((size_t)blockIdx.x * 256 + threadIdx.x) * 4;   // grid 192, exact (196608)
    const float* W = (i < 65536) ? Wq : ((i < 131072) ? Wk : Wv);
    size_t off = i & 65535;
    float4 v = *(const float4*)(W + off);
    split4(v, (__nv_bfloat162*)(g_WH + i), (__nv_bfloat162*)(g_WL + i));
}

// ---------------- cp.async helpers ----------------
__device__ __forceinline__ void cp16(void* dst, const void* src) {
    unsigned int d = (unsigned int)__cvta_generic_to_shared(dst);
    asm volatile("cp.async.cg.shared.global [%0], [%1], 16;\n" :: "r"(d), "l"(src));
}
__device__ __forceinline__ void cp_commit() {
    asm volatile("cp.async.commit_group;\n");
}
template <int N>
__device__ __forceinline__ void cp_wait() {
    asm volatile("cp.async.wait_group %0;\n" :: "n"(N));
}

// ---------------- K1: QKV GEMM, bf16x3 split wmma (unchanged, proven) ----------------
#define STG_BYTES 37888
#define GEMM_SMEM (2*STG_BYTES)

__global__ void __launch_bounds__(256, 2) k_gemm_tc(
    const float* __restrict__ bq, const float* __restrict__ bk,
    const float* __restrict__ bv)
{
    extern __shared__ __align__(16) char sm[];

    int mat = blockIdx.y >> 1;
    int n0  = (blockIdx.y & 1) << 7;
    int m0  = blockIdx.x << 7;
    const __nv_bfloat16* WH = g_WH + mat * 65536;
    const __nv_bfloat16* WL = g_WL + mat * 65536;
    const float* bias = (mat == 0) ? bq : ((mat == 1) ? bk : bv);
    float* out        = (mat == 0) ? g_Qlin : ((mat == 1) ? g_Klin : g_V);

    int t = threadIdx.x;
    int warp = t >> 5, lane = t & 31;
    int wm = warp & 3, wn = warp >> 2;

    int ar0 = t >> 2,        ac = (t & 3) * 8;
    int br0 = t >> 4,        bc = (t & 15) * 8;
    int gm0 = m0 + ar0;       if (gm0 >= NPTS) gm0 = NPTS - 1;
    int gm1 = m0 + ar0 + 64;  if (gm1 >= NPTS) gm1 = NPTS - 1;

    wmma::fragment<wmma::accumulator, 16, 16, 16, float> acc[2][4];
#pragma unroll
    for (int i = 0; i < 2; i++)
#pragma unroll
        for (int j = 0; j < 4; j++) wmma::fill_fragment(acc[i][j], 0.f);

    auto issue = [&](int c, int s) {
        char* base = sm + s * STG_BYTES;
        __nv_bfloat16 (*Ah)[40]  = (__nv_bfloat16(*)[40])(base);
        __nv_bfloat16 (*Al)[40]  = (__nv_bfloat16(*)[40])(base + 10240);
        __nv_bfloat16 (*Bh)[136] = (__nv_bfloat16(*)[136])(base + 20480);
        __nv_bfloat16 (*Bl)[136] = (__nv_bfloat16(*)[136])(base + 29184);
        int k0 = c * 32;
        cp16(&Ah[ar0][ac],      g_featH + (size_t)gm0 * CC + k0 + ac);
        cp16(&Ah[ar0 + 64][ac], g_featH + (size_t)gm1 * CC + k0 + ac);
        cp16(&Al[ar0][ac],      g_featL + (size_t)gm0 * CC + k0 + ac);
        cp16(&Al[ar0 + 64][ac], g_featL + (size_t)gm1 * CC + k0 + ac);
        cp16(&Bh[br0][bc],      WH + (size_t)(k0 + br0) * CC + n0 + bc);
        cp16(&Bh[br0 + 16][bc], WH + (size_t)(k0 + br0 + 16) * CC + n0 + bc);
        cp16(&Bl[br0][bc],      WL + (size_t)(k0 + br0) * CC + n0 + bc);
        cp16(&Bl[br0 + 16][bc], WL + (size_t)(k0 + br0 + 16) * CC + n0 + bc);
        cp_commit();
    };

    issue(0, 0);
    issue(1, 1);

    for (int c = 0; c < 8; c++) {
        if (c + 1 < 8) cp_wait<1>(); else cp_wait<0>();
        __syncthreads();
        char* base = sm + (c & 1) * STG_BYTES;
        __nv_bfloat16 (*Ah)[40]  = (__nv_bfloat16(*)[40])(base);
        __nv_bfloat16 (*Al)[40]  = (__nv_bfloat16(*)[40])(base + 10240);
        __nv_bfloat16 (*Bh)[136] = (__nv_bfloat16(*)[136])(base + 20480);
        __nv_bfloat16 (*Bl)[136] = (__nv_bfloat16(*)[136])(base + 29184);
#pragma unroll
        for (int kk = 0; kk < 32; kk += 16) {
            wmma::fragment<wmma::matrix_a, 16, 16, 16, __nv_bfloat16, wmma::row_major> ah[2], al[2];
#pragma unroll
            for (int i = 0; i < 2; i++) {
                wmma::load_matrix_sync(ah[i], &Ah[wm * 32 + i * 16][kk], 40);
                wmma::load_matrix_sync(al[i], &Al[wm * 32 + i * 16][kk], 40);
            }
#pragma unroll
            for (int j = 0; j < 4; j++) {
                wmma::fragment<wmma::matrix_b, 16, 16, 16, __nv_bfloat16, wmma::row_major> bh, bl;
                wmma::load_matrix_sync(bh, &Bh[kk][wn * 64 + j * 16], 136);
                wmma::load_matrix_sync(bl, &Bl[kk][wn * 64 + j * 16], 136);
#pragma unroll
                for (int i = 0; i < 2; i++) {
                    wmma::mma_sync(acc[i][j], ah[i], bh, acc[i][j]);
                    wmma::mma_sync(acc[i][j], ah[i], bl, acc[i][j]);
                    wmma::mma_sync(acc[i][j], al[i], bh, acc[i][j]);
                }
            }
        }
        __syncthreads();
        if (c + 2 < 8) issue(c + 2, c & 1);
    }

    float (*ob)[68] = (float(*)[68])(sm + warp * 8704);
#pragma unroll
    for (int i = 0; i < 2; i++)
#pragma unroll
        for (int j = 0; j < 4; j++)
            wmma::store_matrix_sync(&ob[i * 16][j * 16], acc[i][j], 68, wmma::mem_row_major);
    __syncwarp();

    int col0 = n0 + wn * 64 + lane;
    int col1 = col0 + 32;
    float bb0 = bias[col0], bb1 = bias[col1];
    float s1a = 0.f, s2a = 0.f, s1b = 0.f, s2b = 0.f;
#pragma unroll
    for (int r = 0; r < 32; r++) {
        int gm = m0 + wm * 32 + r;
        if (gm < NPTS) {
            float v0 = ob[r][lane] + bb0;
            float v1 = ob[r][lane + 32] + bb1;
            out[(size_t)gm * CC + col0] = v0;
            out[(size_t)gm * CC + col1] = v1;
            s1a += v0; s2a = fmaf(v0, v0, s2a);
            s1b += v1; s2b = fmaf(v1, v1, s2b);
        }
    }
    if (mat < 2) {
        int base = (mat == 0) ? 0 : 512;
        atomicAdd(&g_ds[base + col0],       (double)s1a);
        atomicAdd(&g_ds[base + 256 + col0], (double)s2a);
        atomicAdd(&g_ds[base + col1],       (double)s1b);
        atomicAdd(&g_ds[base + 256 + col1], (double)s2b);
    }
}

// ---------------- K3: pos second moments ----------------
__global__ void k_posmom(const float* __restrict__ coord, const int* __restrict__ ridx) {
    int i = blockIdx.x * 256 + threadIdx.x;
    int n = i >> 4;
    int r = ridx[i];
    float px = 0, py = 0, pz = 0;
    if (r >= 0) {
        px = coord[r * 3 + 0] - coord[n * 3 + 0];
        py = coord[r * 3 + 1] - coord[n * 3 + 1];
        pz = coord[r * 3 + 2] - coord[n * 3 + 2];
    }
    float v[9] = {px, py, pz, px * px, py * py, pz * pz, px * py, px * pz, py * pz};
    __shared__ float red[8][9];
    int lane = threadIdx.x & 31, w = threadIdx.x >> 5;
#pragma unroll
    for (int j = 0; j < 9; j++)
#pragma unroll
        for (int off = 16; off; off >>= 1)
            v[j] += __shfl_down_sync(0xffffffffu, v[j], off);
    if (lane == 0)
#pragma unroll
        for (int j = 0; j < 9; j++) red[w][j] = v[j];
    __syncthreads();
    if (threadIdx.x < 9) {
        float s = 0;
        for (int w2 = 0; w2 < 8; w2++) s += red[w2][threadIdx.x];
        atomicAdd(&g_ds[1024 + threadIdx.x], (double)s);
    }
}

// ---------------- K4: fold BN params; build Wp2g (fp16 hi/lo), glb ----------------
__global__ void k_final1(
    const float* __restrict__ gq, const float* __restrict__ betaq,
    const float* __restrict__ gk, const float* __restrict__ betak,
    const float* __restrict__ Wp1, const float* __restrict__ bp1,
    const float* __restrict__ gp, const float* __restrict__ betap,
    const float* __restrict__ Wp2, const float* __restrict__ bp2,
    const float* __restrict__ w_gl)
{
    int c = threadIdx.x;
    double invN = 1.0 / (double)NPTS;
    {
        double mu = g_ds[c] * invN;
        double var = g_ds[256 + c] * invN - mu * mu;
        float a = (float)((double)gq[c] / sqrt(var + 1e-5));
        g_aq[c] = a; g_bq[c] = betaq[c] - (float)mu * a;
    }
    {
        double mu = g_ds[512 + c] * invN;
        double var = g_ds[768 + c] * invN - mu * mu;
        float a = (float)((double)gk[c] / sqrt(var + 1e-5));
        g_ak[c] = a; g_bk[c] = betak[c] - (float)mu * a;
    }
    {
        double sx = g_ds[1024], sy = g_ds[1025], sz = g_ds[1026];
        double xx = g_ds[1027], yy = g_ds[1028], zz = g_ds[1029];
        double xy = g_ds[1030], xz = g_ds[1031], yz = g_ds[1032];
        double w0 = Wp1[c], w1 = Wp1[256 + c], w2 = Wp1[512 + c], b = bp1[c];
        double invNS = 1.0 / (double)NSROWS;
        double sw = sx * w0 + sy * w1 + sz * w2;
        double mean = sw * invNS + b;
        double ex2 = (w0 * w0 * xx + w1 * w1 * yy + w2 * w2 * zz
                      + 2.0 * (w0 * w1 * xy + w0 * w2 * xz + w1 * w2 * yz)
                      + 2.0 * b * sw) * invNS + b * b;
        double var = ex2 - mean * mean;
        float a = (float)((double)gp[c] / sqrt(var + 1e-5));
        g_ap[c]  = a;
        g_bpf[c] = (float)((double)a * b + (double)betap[c] - mean * a);
    }
#pragma unroll
    for (int g = 0; g < GG; g++) {
        float s = 0;
#pragma unroll
        for (int i2 = 0; i2 < 16; i2++)
            s = fmaf(Wp2[(size_t)c * CC + g * 16 + i2], w_gl[g * 16 + i2], s);
        __half hh = __float2half_rn(s);
        g_Wp2gH[c * GG + g] = hh;
        g_Wp2gL[c * GG + g] = __float2half_rn(s - __half2float(hh));
    }
    if (c < GG) {
        float s = 0;
#pragma unroll
        for (int i2 = 0; i2 < 16; i2++) s = fmaf(bp2[c * 16 + i2], w_gl[c * 16 + i2], s);
        g_glb[c] = s;
    }
}

// ---------------- K5: group-folded q,k vectors ----------------
__global__ void __launch_bounds__(256) k_qkgroup(const float* __restrict__ w_gl) {
    int lane = threadIdx.x & 31, warp = threadIdx.x >> 5;
    int n = blockIdx.x * 8 + warp;
#pragma unroll
    for (int j = 0; j < 8; j++) {
        int c = lane + 32 * j;
        float wg = w_gl[c];
        float vq = fmaxf(fmaf(g_aq[c], g_Qlin[(size_t)n * CC + c], g_bq[c]), 0.f) * wg;
        float vk = fmaxf(fmaf(g_ak[c], g_Klin[(size_t)n * CC + c], g_bk[c]), 0.f) * wg;
#pragma unroll
        for (int off = 8; off; off >>= 1) {
            vq += __shfl_down_sync(0xffffffffu, vq, off, 16);
            vk += __shfl_down_sync(0xffffffffu, vk, off, 16);
        }
        if (lane == 0)  { g_qg[n * GG + 2 * j]     = vq; g_kg[n * GG + 2 * j]     = vk; }
        if (lane == 16) { g_qg[n * GG + 2 * j + 1] = vq; g_kg[n * GG + 2 * j + 1] = vk; }
    }
}

// ---------------- K6: w_pre logits on tensor cores, h in single fp16 ----------------
__global__ void __launch_bounds__(256, 2) k_wpre_tc(
    const float* __restrict__ coord, const int* __restrict__ ridx,
    const float* __restrict__ Wp1)
{
    __shared__ __align__(32) __half hA[128][40];
    __shared__ __align__(32) __half BH[256][16];
    __shared__ __align__(32) __half BL[256][16];
    __shared__ __align__(16) float4 P4[256];
    __shared__ float Bpf[256];
    __shared__ float px[128], py[128], pz[128];
    __shared__ int rw[128];
    __shared__ float glb_s[16];
    __shared__ __align__(32) float ep[8][16][24];

    int t = threadIdx.x;
    int warp = t >> 5;
    P4[t] = make_float4(Wp1[t], Wp1[256 + t], Wp1[512 + t], g_ap[t]);
    Bpf[t] = g_bpf[t];
    for (int l = t; l < 4096; l += 256) {
        ((__half*)BH)[l] = g_Wp2gH[l];
        ((__half*)BL)[l] = g_Wp2gL[l];
    }
    if (t < 16) glb_s[t] = g_glb[t];
    int base = blockIdx.x * 128;
    if (t < 128) {
        int row = base + t;
        int r = ridx[row];
        rw[t] = r;
        float x = 0, y = 0, z = 0;
        if (r >= 0) {
            int n = row >> 4;
            x = coord[r * 3 + 0] - coord[n * 3 + 0];
            y = coord[r * 3 + 1] - coord[n * 3 + 1];
            z = coord[r * 3 + 2] - coord[n * 3 + 2];
        }
        px[t] = x; py[t] = y; pz[t] = z;
    }
    __syncthreads();

    wmma::fragment<wmma::accumulator, 16, 16, 16, float> acc;
    wmma::fill_fragment(acc, 0.f);
    int rloc = t >> 1, cb = (t & 1) * 16;
    float x = px[rloc], y = py[rloc], z = pz[rloc];

    for (int c = 0; c < 8; c++) {
        int k0 = c * 32;
#pragma unroll
        for (int i = 0; i < 16; i += 2) {
            int c0 = k0 + cb + i;
            float4 p0 = P4[c0], p1 = P4[c0 + 1];
            float h0 = fmaxf(fmaf(p0.w, fmaf(z, p0.z, fmaf(y, p0.y, x * p0.x)), Bpf[c0]), 0.f);
            float h1 = fmaxf(fmaf(p1.w, fmaf(z, p1.z, fmaf(y, p1.y, x * p1.x)), Bpf[c0 + 1]), 0.f);
            *(__half2*)&hA[rloc][cb + i] = __floats2half2_rn(h0, h1);
        }
        __syncthreads();
#pragma unroll
        for (int kk = 0; kk < 32; kk += 16) {
            wmma::fragment<wmma::matrix_a, 16, 16, 16, __half, wmma::row_major> a;
            wmma::load_matrix_sync(a, &hA[warp * 16][kk], 40);
            wmma::fragment<wmma::matrix_b, 16, 16, 16, __half, wmma::row_major> bh, bl;
            wmma::load_matrix_sync(bh, &BH[k0 + kk][0], 16);
            wmma::load_matrix_sync(bl, &BL[k0 + kk][0], 16);
            wmma::mma_sync(acc, a, bh, acc);
            wmma::mma_sync(acc, a, bl, acc);
        }
        __syncthreads();
    }
    wmma::store_matrix_sync(&ep[warp][0][0], acc, 24, wmma::mem_row_major);
    __syncthreads();
    {
        int rl2 = t >> 1, gb = (t & 1) * 8;
        int row = base + rl2;
        int n = row >> 4;
        int r = rw[rl2];
        const float* epp = &ep[rl2 >> 4][rl2 & 15][0];
#pragma unroll
        for (int j = 0; j < 8; j++) {
            int g = gb + j;
            float kgv = (r >= 0) ? g_kg[(size_t)r * GG + g] : 0.f;
            g_wpre[(size_t)row * GG + g] = epp[g] + kgv - g_qg[(size_t)n * GG + g] + glb_s[g];
        }
    }
}

// ---------------- K7: group stats of w_pre ----------------
__global__ void k_wstats() {
    __shared__ float ssum[16], ssq[16];
    int t = threadIdx.x;
    if (t < 16) { ssum[t] = 0.f; ssq[t] = 0.f; }
    __syncthreads();
    int g = t & 15;
    float s1 = 0, s2 = 0;
    for (int row = blockIdx.x * 16 + (t >> 4); row < NSROWS; row += gridDim.x * 16) {
        float x = g_wpre[(size_t)row * GG + g];
        s1 += x; s2 = fmaf(x, x, s2);
    }
    atomicAdd(&ssum[g], s1);
    atomicAdd(&ssq[g], s2);
    __syncthreads();
    if (t < 16) {
        atomicAdd(&g_ds[1040 + t], (double)ssum[t]);
        atomicAdd(&g_ds[1056 + t], (double)ssq[t]);
    }
}

// ---------------- K8: fold group BN ----------------
__global__ void k_final2(const float* __restrict__ g_gl, const float* __restrict__ beta_gl) {
    int g = threadIdx.x;
    if (g < 16) {
        double invNS = 1.0 / (double)NSROWS;
        double mu  = g_ds[1040 + g] * invNS;
        double var = g_ds[1056 + g] * invNS - mu * mu;
        float a = (float)((double)g_gl[g] / sqrt(var + 1e-5));
        g_aw[g] = a; g_bw[g] = beta_gl[g] - (float)mu * a;
    }
}

// ---------------- K9: fused per-point: logits -> softmax -> gathered V + Hw fp16 ----------------
__global__ void __launch_bounds__(256) k_pointG(
    const float* __restrict__ coord, const int* __restrict__ ridx,
    const float* __restrict__ Wp1,  const float* __restrict__ bp2,
    const float* __restrict__ Wwe,  const float* __restrict__ bwe,
    float* __restrict__ out)
{
    __shared__ float rl[16][17];
    __shared__ float lg[16][17];
    __shared__ float wsm[16][17];
    __shared__ float wsum[16];
    __shared__ float Wwe_s[16][16];
    __shared__ float bwe_s[16];
    __shared__ float psx[16], psy[16], psz[16];
    __shared__ int   rs[16];

    int n = blockIdx.x, t = threadIdx.x;
    Wwe_s[t >> 4][t & 15] = Wwe[t];
    if (t < 16) {
        bwe_s[t] = bwe[t];
        int r = ridx[n * SS + t];
        rs[t] = r;
        float x = 0, y = 0, z = 0;
        if (r >= 0) {
            x = coord[r * 3 + 0] - coord[n * 3 + 0];
            y = coord[r * 3 + 1] - coord[n * 3 + 1];
            z = coord[r * 3 + 2] - coord[n * 3 + 2];
        }
        psx[t] = x; psy[t] = y; psz[t] = z;
    }
    int s = t >> 4, g = t & 15;
    {
        float x = g_wpre[(size_t)n * 256 + t];
        rl[s][g] = fmaxf(fmaf(g_aw[g], x, g_bw[g]), 0.f);
    }
    __syncthreads();
    {
        float acc = bwe_s[g];
#pragma unroll
        for (int gp2 = 0; gp2 < 16; gp2++)
            acc = fmaf(rl[s][gp2], Wwe_s[gp2][g], acc);
        lg[s][g] = acc;
    }
    __syncthreads();
    if (t < 16) {
        float m = -1e30f;
#pragma unroll
        for (int ss2 = 0; ss2 < 16; ss2++) m = fmaxf(m, lg[ss2][t]);
        float sum = 0;
        float e[16];
#pragma unroll
        for (int ss2 = 0; ss2 < 16; ss2++) { e[ss2] = expf(lg[ss2][t] - m); sum += e[ss2]; }
        float inv = 1.f / sum;
        float ws = 0;
#pragma unroll
        for (int ss2 = 0; ss2 < 16; ss2++) {
            float w = (rs[ss2] >= 0) ? e[ss2] * inv : 0.f;
            wsm[ss2][t] = w; ws += w;
        }
        wsum[t] = ws;
    }
    __syncthreads();

    int c = t, gc = c >> 4;
    float hw[16];
#pragma unroll
    for (int gg = 0; gg < 16; gg++) hw[gg] = 0.f;
    float out1 = wsum[gc] * bp2[c];
    float w1c = Wp1[c], w2c = Wp1[256 + c], w3c = Wp1[512 + c];
    float apc = g_ap[c], bpc = g_bpf[c];
#pragma unroll
    for (int ss2 = 0; ss2 < 16; ss2++) {
        int r = rs[ss2];
        if (r >= 0) {
            out1 = fmaf(wsm[ss2][gc], g_V[(size_t)r * CC + c], out1);
            float pd = fmaf(psz[ss2], w3c, fmaf(psy[ss2], w2c, psx[ss2] * w1c));
            float h = fmaxf(fmaf(apc, pd, bpc), 0.f);
#pragma unroll
            for (int gg = 0; gg < 16; gg++)
                hw[gg] = fmaf(wsm[ss2][gg], h, hw[gg]);
        }
    }
    out[(size_t)n * CC + c] = out1;
#pragma unroll
    for (int gg = 0; gg < 16; gg++)
        g_Hw16[(size_t)n * 4096 + gg * 256 + c] = __float2half_rn(hw[gg]);
}

// ---------------- K10: projection GEMM on tensor cores, A single fp16 ----------------
__global__ void __launch_bounds__(256, 2) k_projH_tc(
    const float* __restrict__ Wp2, float* __restrict__ out)
{
    __shared__ __align__(32) __half Asm[2][128][40];
    __shared__ __align__(32) __half BH[256][16];
    __shared__ __align__(32) __half BL[256][16];

    int g = blockIdx.y;
    int n0 = blockIdx.x * 128;
    int t = threadIdx.x;
    int warp = t >> 5;

    for (int l = t; l < 4096; l += 256) {
        float w = Wp2[(size_t)(l >> 4) * CC + g * 16 + (l & 15)];
        __half h = __float2half_rn(w);
        ((__half*)BH)[l] = h;
        ((__half*)BL)[l] = __float2half_rn(w - __half2float(h));
    }

    auto issueA = [&](int c, int s) {
#pragma unroll
        for (int q = 0; q < 2; q++) {
            int idx = t + q * 256;
            int row = idx >> 2, seg = idx & 3;
            int nn = n0 + row; if (nn >= NPTS) nn = NPTS - 1;
            cp16(&Asm[s][row][seg * 8],
                 g_Hw16 + (size_t)nn * 4096 + g * 256 + c * 32 + seg * 8);
        }
        cp_commit();
    };
    issueA(0, 0); issueA(1, 1);

    wmma::fragment<wmma::accumulator, 16, 16, 16, float> acc;
    wmma::fill_fragment(acc, 0.f);

    for (int c = 0; c < 8; c++) {
        if (c + 1 < 8) cp_wait<1>(); else cp_wait<0>();
        __syncthreads();
#pragma unroll
        for (int kk = 0; kk < 32; kk += 16) {
            wmma::fragment<wmma::matrix_a, 16, 16, 16, __half, wmma::row_major> a;
            wmma::load_matrix_sync(a, &Asm[c & 1][warp * 16][kk], 40);
            wmma::fragment<wmma::matrix_b, 16, 16, 16, __half, wmma::row_major> bh, bl;
            wmma::load_matrix_sync(bh, &BH[c * 32 + kk][0], 16);
            wmma::load_matrix_sync(bl, &BL[c * 32 + kk][0], 16);
            wmma::mma_sync(acc, a, bh, acc);
            wmma::mma_sync(acc, a, bl, acc);
        }
        __syncthreads();
        if (c + 2 < 8) issueA(c + 2, c & 1);
    }

    float* ep = (float*)Asm;   // reuse A smem for epilogue staging (12288 B)
    wmma::store_matrix_sync(ep + warp * 384, acc, 24, wmma::mem_row_major);
    __syncthreads();
    {
        int rl = t >> 1, jb = (t & 1) * 8;
        int nn = n0 + rl;
        if (nn < NPTS) {
            const float* epp = ep + (rl >> 4) * 384 + (rl & 15) * 24 + jb;
            float4* p0 = (float4*)(out + (size_t)nn * CC + g * 16 + jb);
            float4 c0 = p0[0], c1 = p0[1];
            c0.x += epp[0]; c0.y += epp[1]; c0.z += epp[2]; c0.w += epp[3];
            c1.x += epp[4]; c1.y += epp[5]; c1.z += epp[6]; c1.w += epp[7];
            p0[0] = c0; p0[1] = c1;
        }
    }
}

// ---------------- launch ----------------
extern "C" void kernel_launch(void* const* d_in, const int* in_sizes, int n_in,
                              void* d_out, int out_size) {
    const float* feat   = (const float*)d_in[0];
    const float* coord  = (const float*)d_in[1];
    const int*   ridx   = (const int*)  d_in[2];
    const float* Wq     = (const float*)d_in[3];
    const float* bq     = (const float*)d_in[4];
    const float* gq     = (const float*)d_in[5];
    const float* betaq  = (const float*)d_in[6];
    const float* Wk     = (const float*)d_in[7];
    const float* bk     = (const float*)d_in[8];
    const float* gk     = (const float*)d_in[9];
    const float* betak  = (const float*)d_in[10];
    const float* Wv     = (const float*)d_in[11];
    const float* bv     = (const float*)d_in[12];
    const float* Wp1    = (const float*)d_in[13];
    const float* bp1    = (const float*)d_in[14];
    const float* gp     = (const float*)d_in[15];
    const float* betap  = (const float*)d_in[16];
    const float* Wp2    = (const float*)d_in[17];
    const float* bp2    = (const float*)d_in[18];
    const float* w_gl   = (const float*)d_in[19];
    const float* g_gl   = (const float*)d_in[20];
    const float* betagl = (const float*)d_in[21];
    const float* Wwe    = (const float*)d_in[22];
    const float* bwe    = (const float*)d_in[23];
    float* out = (float*)d_out;

    cudaFuncSetAttribute(k_gemm_tc, cudaFuncAttributeMaxDynamicSharedMemorySize, GEMM_SMEM);

    k_zero<<<5, 256>>>();
    k_cvt_feat<<<25000, 256>>>(feat);
    k_cvt_W<<<192, 256>>>(Wq, Wk, Wv);
    dim3 gtc((NPTS + 127) / 128, 6);
    k_gemm_tc<<<gtc, 256, GEMM_SMEM>>>(bq, bk, bv);
    k_posmom<<<NSROWS / 256, 256>>>(coord, ridx);
    k_final1<<<1, 256>>>(gq, betaq, gk, betak, Wp1, bp1, gp, betap, Wp2, bp2, w_gl);
    k_qkgroup<<<NPTS / 8, 256>>>(w_gl);
    k_wpre_tc<<<NSROWS / 128, 256>>>(coord, ridx, Wp1);
    k_wstats<<<512, 256>>>();
    k_final2<<<1, 32>>>(g_gl, betagl);
    k_pointG<<<NPTS, 256>>>(coord, ridx, Wp1, bp2, Wwe, bwe, out);
    dim3 gg2((NPTS + 127) / 128, 16);
    k_projH_tc<<<gg2, 256>>>(Wp2, out);
}